// round 10
// baseline (speedup 1.0000x reference)
#include <cuda_runtime.h>
#include <cuda_fp16.h>
#include <cstdint>

// FiberConv collapsed to GEMM: C[400000,384] = x[400000,384] @ Bt^T + bias
//   Bt[n=(t*32+o)][k=(s*32+i)] = sum_a edge[t,s,a] * W[o*32+i, a]
// Single-pass fp16 (xh*Bh), rel_err ~2.9e-4 (calibrated R6-R9).
// R10: fully async producer path. x arrives raw fp32 via cp.async (no LDG
// latency in thread context); a smem->smem pass (LDS.128 -> cvt.f16x2 ->
// STS.64, thread-local data) builds the fp16 A tile one chunk ahead.
// Rings: Xf32 x2, A16 x3, B16 x3 = 96KB/CTA -> 2 CTAs/SM.

#define NDIM 384
#define KDIM 384
#define BATCH 400000

#define BM 128
#define BN 128
#define BK 32
#define NTHREADS 256
#define NCHUNK (KDIM / BK)     // 12

#define XSTRB 144              // fp32 x row stride bytes (32*4=128 pad to 144)
#define ASTRB 80               // fp16 row stride bytes (16B-aligned, odd*16)
#define XTILE (128 * XSTRB)    // 18432
#define ATILE (128 * ASTRB)    // 10240

#define OFF_X 0
#define OFF_A (2 * XTILE)              // 36864
#define OFF_B (OFF_A + 3 * ATILE)      // 67584
#define SMEM_DYN (OFF_B + 3 * ATILE)   // 98304 (96KB) -> 2 CTAs/SM

__device__ __half g_Bh[NDIM * KDIM];

__global__ void fiber_precompute(const float* __restrict__ edge,
                                 const float* __restrict__ W) {
    int idx = blockIdx.x * blockDim.x + threadIdx.x;
    if (idx >= NDIM * KDIM) return;
    int n = idx / KDIM, k = idx % KDIM;
    int t = n >> 5, o = n & 31, s = k >> 5, i = k & 31;
    const float* e = edge + (t * 12 + s) * 3;
    const float* w = W + (o * 32 + i) * 3;
    float v = e[0] * w[0] + e[1] * w[1] + e[2] * w[2];
    g_Bh[idx] = __float2half_rn(v);
}

// ---------------- PTX helpers ----------------
__device__ __forceinline__ uint32_t smem_u32(const void* p) {
    uint32_t a;
    asm("{ .reg .u64 t; cvta.to.shared.u64 t, %1; cvt.u32.u64 %0, t; }" : "=r"(a) : "l"(p));
    return a;
}
__device__ __forceinline__ void ldsm_x4(uint32_t& r0, uint32_t& r1, uint32_t& r2,
                                        uint32_t& r3, uint32_t addr) {
    asm volatile("ldmatrix.sync.aligned.m8n8.x4.shared.b16 {%0,%1,%2,%3}, [%4];"
                 : "=r"(r0), "=r"(r1), "=r"(r2), "=r"(r3) : "r"(addr));
}
__device__ __forceinline__ void mma_f16(float& d0, float& d1, float& d2, float& d3,
                                        uint32_t a0, uint32_t a1, uint32_t a2, uint32_t a3,
                                        uint32_t b0, uint32_t b1) {
    asm volatile(
        "mma.sync.aligned.m16n8k16.row.col.f32.f16.f16.f32 "
        "{%0,%1,%2,%3}, {%4,%5,%6,%7}, {%8,%9}, {%0,%1,%2,%3};"
        : "+f"(d0), "+f"(d1), "+f"(d2), "+f"(d3)
        : "r"(a0), "r"(a1), "r"(a2), "r"(a3), "r"(b0), "r"(b1));
}
__device__ __forceinline__ void cp_async16(uint32_t dst, const void* src) {
    asm volatile("cp.async.cg.shared.global [%0], [%1], 16;" :: "r"(dst), "l"(src));
}
#define CP_COMMIT() asm volatile("cp.async.commit_group;" ::: "memory")
#define CP_WAIT0()  asm volatile("cp.async.wait_group 0;" ::: "memory")
#define CP_WAIT1()  asm volatile("cp.async.wait_group 1;" ::: "memory")

__device__ __forceinline__ uint32_t cvt_f16x2(float a, float b) {
    uint32_t r;
    asm("cvt.rn.f16x2.f32 %0, %2, %1;" : "=r"(r) : "f"(a), "f"(b));
    return r;
}

// ---------------- main GEMM ----------------
__global__ void __launch_bounds__(NTHREADS, 2)
fiber_gemm_hmma(const float* __restrict__ x, const float* __restrict__ bias,
                float* __restrict__ out) {
    extern __shared__ char smem[];
    const uint32_t sbase = smem_u32(smem);

    const int tid  = threadIdx.x;
    const int lane = tid & 31;
    const int warp = tid >> 5;
    const int wm = warp >> 2;          // 0..1
    const int wn = warp & 3;           // 0..3
    const int bn = blockIdx.x;         // 0..2
    const int bm = blockIdx.y;         // 0..3124

    const float* xblk = x + (size_t)bm * BM * KDIM;
    const __half* gBh = g_Bh + (size_t)bn * BN * KDIM;

    float acc[4][4][4];
    #pragma unroll
    for (int a = 0; a < 4; a++)
        #pragma unroll
        for (int b = 0; b < 4; b++)
            #pragma unroll
            for (int c = 0; c < 4; c++) acc[a][b][c] = 0.f;

    const uint32_t a_lane_off = (uint32_t)((wm * 64 + (lane & 15)) * ASTRB + (lane >> 4) * 16);
    const uint32_t b_lane_off = (uint32_t)((wn * 32 + ((lane >> 4) << 3) + (lane & 7)) * ASTRB
                                           + ((lane >> 3) & 1) * 16);

    // X chunk: 128 rows x 32 fp32 = 16KB = 1024 x 16B slots; 4 per thread.
    // slot -> r = slot>>3 (8 segs/row), seg = slot&7.
    // B chunk: 128 rows x 32 fp16 = 8KB = 512 x 16B slots; 2 per thread.
    auto cp_group = [&](int c) {
        uint32_t dX = sbase + OFF_X + (c & 1) * XTILE;
        #pragma unroll
        for (int it = 0; it < 4; it++) {
            int slot = it * NTHREADS + tid;
            int r = slot >> 3, seg = slot & 7;
            cp_async16(dX + (uint32_t)(r * XSTRB + seg * 16),
                       xblk + (size_t)r * KDIM + c * BK + seg * 4);
        }
        uint32_t dB = sbase + OFF_B + (c % 3) * ATILE;
        #pragma unroll
        for (int it = 0; it < 2; it++) {
            int slot = it * NTHREADS + tid;
            int r = slot >> 2, seg = slot & 3;
            cp_async16(dB + (uint32_t)(r * ASTRB + seg * 16),
                       gBh + (size_t)r * KDIM + c * BK + seg * 8);
        }
        CP_COMMIT();
    };

    // convert X(c) fp32 -> A16(c): each thread converts exactly the 4x16B it
    // cp.async'd (same slot mapping), so no extra barrier is needed.
    auto convert = [&](int c) {
        uint32_t sX = sbase + OFF_X + (c & 1) * XTILE;
        uint32_t dA = sbase + OFF_A + (c % 3) * ATILE;
        #pragma unroll
        for (int it = 0; it < 4; it++) {
            int slot = it * NTHREADS + tid;
            int r = slot >> 3, seg = slot & 7;
            float4 v;
            asm volatile("ld.shared.v4.f32 {%0,%1,%2,%3}, [%4];"
                         : "=f"(v.x), "=f"(v.y), "=f"(v.z), "=f"(v.w)
                         : "r"(sX + (uint32_t)(r * XSTRB + seg * 16)));
            uint32_t h01 = cvt_f16x2(v.x, v.y);
            uint32_t h23 = cvt_f16x2(v.z, v.w);
            asm volatile("st.shared.v2.b32 [%0], {%1,%2};"
                         :: "r"(dA + (uint32_t)(r * ASTRB + seg * 8)), "r"(h01), "r"(h23));
        }
    };

    auto mma_chunk = [&](int c) {
        const uint32_t Ah = sbase + OFF_A + (c % 3) * ATILE;
        const uint32_t Bh = sbase + OFF_B + (c % 3) * ATILE;
        #pragma unroll
        for (int ks = 0; ks < BK / 16; ks++) {
            const uint32_t kso = ks * 32;
            uint32_t af[4][4], bh[2][4];
            #pragma unroll
            for (int mi = 0; mi < 4; mi++)
                ldsm_x4(af[mi][0], af[mi][1], af[mi][2], af[mi][3],
                        Ah + a_lane_off + mi * 16 * ASTRB + kso);
            #pragma unroll
            for (int pj = 0; pj < 2; pj++)
                ldsm_x4(bh[pj][0], bh[pj][1], bh[pj][2], bh[pj][3],
                        Bh + b_lane_off + pj * 16 * ASTRB + kso);
            #pragma unroll
            for (int mi = 0; mi < 4; mi++)
                #pragma unroll
                for (int ni = 0; ni < 4; ni++)
                    mma_f16(acc[mi][ni][0], acc[mi][ni][1], acc[mi][ni][2], acc[mi][ni][3],
                            af[mi][0], af[mi][1], af[mi][2], af[mi][3],
                            bh[ni >> 1][(ni & 1) * 2], bh[ni >> 1][(ni & 1) * 2 + 1]);
        }
    };

    // prologue: stage chunks 0 and 1; convert chunk 0
    cp_group(0);
    cp_group(1);
    CP_WAIT1();              // group(0) complete
    convert(0);
    __syncthreads();

    for (int c = 0; c < NCHUNK; c++) {
        if (c + 2 < NCHUNK) {
            cp_group(c + 2);
            CP_WAIT1();      // completes group(c+1); group(c+2) stays in flight
        } else {
            CP_WAIT0();      // drain remaining
        }
        if (c + 1 < NCHUNK) convert(c + 1);
        mma_chunk(c);
        __syncthreads();
    }

    // ---- epilogue: registers -> global (float2 stores) + bias ----
    float* oblk = out + (size_t)bm * BM * NDIM + bn * BN;
    const int r0 = wm * 64 + (lane >> 2);
    const int c0 = wn * 32 + (lane & 3) * 2;
    #pragma unroll
    for (int ni = 0; ni < 4; ni++) {
        const int col = c0 + ni * 8;
        const float b0 = bias[col & 31];
        const float b1 = bias[(col + 1) & 31];
        #pragma unroll
        for (int mi = 0; mi < 4; mi++) {
            const int row = r0 + mi * 16;
            float2 v0 = make_float2(acc[mi][ni][0] + b0, acc[mi][ni][1] + b1);
            float2 v1 = make_float2(acc[mi][ni][2] + b0, acc[mi][ni][3] + b1);
            *(float2*)(oblk + (size_t)row * NDIM + col) = v0;
            *(float2*)(oblk + (size_t)(row + 8) * NDIM + col) = v1;
        }
    }
}

// ---------------------------------------------------------------------------
extern "C" void kernel_launch(void* const* d_in, const int* in_sizes, int n_in,
                              void* d_out, int out_size) {
    const float* x    = (const float*)d_in[0];   // [400000, 384]
    const float* edge = (const float*)d_in[1];   // [12, 12, 3]
    const float* W    = (const float*)d_in[2];   // [1024, 3]
    const float* bias = (const float*)d_in[3];   // [32]
    float* out = (float*)d_out;                  // [400000, 384]

    cudaFuncSetAttribute(fiber_gemm_hmma,
                         cudaFuncAttributeMaxDynamicSharedMemorySize, SMEM_DYN);

    fiber_precompute<<<(NDIM * KDIM + 255) / 256, 256>>>(edge, W);

    dim3 grid(NDIM / BN, BATCH / BM);   // (3, 3125)
    fiber_gemm_hmma<<<grid, NTHREADS, SMEM_DYN>>>(x, bias, out);
}

// round 11
// speedup vs baseline: 1.0247x; 1.0247x over previous
#include <cuda_runtime.h>
#include <cuda_fp16.h>
#include <cstdint>

// FiberConv collapsed to GEMM: C[400000,384] = x[400000,384] @ Bt^T + bias
//   Bt[n=(t*32+o)][k=(s*32+i)] = sum_a edge[t,s,a] * W[o*32+i, a]
// Single-pass fp16 (xh*Bh), rel_err ~2.9e-4 (calibrated R6-R9).
// R11: BM 128->64, 4 warps/CTA (warp tile 32x64), 4 CTAs/SM. Same total L1
// bytes, but 4 independent barrier domains of 4 warps each instead of 2
// domains of 8 -> less chunk-boundary skew, higher L1/tensor pipe fill.
// L1TEX is the measured co-binding pipe (byte accounting matches ncu R9/R10).

#define NDIM 384
#define KDIM 384
#define BATCH 400000

#define BM 64
#define BN 128
#define BK 64
#define NTHREADS 128
#define NCHUNK (KDIM / BK)                 // 6

#define SSTR 72                            // padded fp16 row stride (144 bytes)
#define ATILE (64 * SSTR * 2)              // 9216
#define BTILE (128 * SSTR * 2)             // 18432
#define STAGE_BYTES (ATILE + BTILE)        // 27648
#define SMEM_DYN (2 * STAGE_BYTES)         // 55296 -> 4 CTAs/SM (221KB)

__device__ __half g_Bh[NDIM * KDIM];

__global__ void fiber_precompute(const float* __restrict__ edge,
                                 const float* __restrict__ W) {
    int idx = blockIdx.x * blockDim.x + threadIdx.x;
    if (idx >= NDIM * KDIM) return;
    int n = idx / KDIM, k = idx % KDIM;
    int t = n >> 5, o = n & 31, s = k >> 5, i = k & 31;
    const float* e = edge + (t * 12 + s) * 3;
    const float* w = W + (o * 32 + i) * 3;
    float v = e[0] * w[0] + e[1] * w[1] + e[2] * w[2];
    g_Bh[idx] = __float2half_rn(v);
}

// ---------------- PTX helpers ----------------
__device__ __forceinline__ uint32_t smem_u32(const void* p) {
    uint32_t a;
    asm("{ .reg .u64 t; cvta.to.shared.u64 t, %1; cvt.u32.u64 %0, t; }" : "=r"(a) : "l"(p));
    return a;
}
__device__ __forceinline__ void ldsm_x4(uint32_t& r0, uint32_t& r1, uint32_t& r2,
                                        uint32_t& r3, uint32_t addr) {
    asm volatile("ldmatrix.sync.aligned.m8n8.x4.shared.b16 {%0,%1,%2,%3}, [%4];"
                 : "=r"(r0), "=r"(r1), "=r"(r2), "=r"(r3) : "r"(addr));
}
__device__ __forceinline__ void mma_f16(float& d0, float& d1, float& d2, float& d3,
                                        uint32_t a0, uint32_t a1, uint32_t a2, uint32_t a3,
                                        uint32_t b0, uint32_t b1) {
    asm volatile(
        "mma.sync.aligned.m16n8k16.row.col.f32.f16.f16.f32 "
        "{%0,%1,%2,%3}, {%4,%5,%6,%7}, {%8,%9}, {%0,%1,%2,%3};"
        : "+f"(d0), "+f"(d1), "+f"(d2), "+f"(d3)
        : "r"(a0), "r"(a1), "r"(a2), "r"(a3), "r"(b0), "r"(b1));
}
__device__ __forceinline__ void cp_async16(uint32_t dst, const void* src) {
    asm volatile("cp.async.cg.shared.global [%0], [%1], 16;" :: "r"(dst), "l"(src));
}
#define CP_COMMIT() asm volatile("cp.async.commit_group;" ::: "memory")
#define CP_WAIT0()  asm volatile("cp.async.wait_group 0;" ::: "memory")

__device__ __forceinline__ uint32_t pack2h(float a, float b) {
    __half ha = __float2half_rn(a), hb = __float2half_rn(b);
    return ((uint32_t)__half_as_ushort(hb) << 16) | __half_as_ushort(ha);
}

// ---------------- main GEMM ----------------
// 4 warps arranged 2x2: warp tile 32 rows x 64 cols (mi=2, ni=8, acc=64 regs)
__global__ void __launch_bounds__(NTHREADS, 4)
fiber_gemm_hmma(const float* __restrict__ x, const float* __restrict__ bias,
                float* __restrict__ out) {
    extern __shared__ char smem[];
    const uint32_t sbase = smem_u32(smem);

    const int tid  = threadIdx.x;
    const int lane = tid & 31;
    const int warp = tid >> 5;
    const int wm = warp >> 1;          // 0..1 (row group of 32)
    const int wn = warp & 1;           // 0..1 (col group of 64)
    const int bn = blockIdx.x;         // 0..2
    const int bm = blockIdx.y;         // 0..6249

    const float* xblk = x + (size_t)bm * BM * KDIM;
    const __half* gBh = g_Bh + (size_t)bn * BN * KDIM;

    float acc[2][8][4];
    #pragma unroll
    for (int a = 0; a < 2; a++)
        #pragma unroll
        for (int b = 0; b < 8; b++)
            #pragma unroll
            for (int c = 0; c < 4; c++) acc[a][b][c] = 0.f;

    const uint32_t a_lane_off = (uint32_t)((wm * 32 + (lane & 15)) * (SSTR * 2) + (lane >> 4) * 16);
    const uint32_t b_lane_off = (uint32_t)((wn * 64 + ((lane >> 4) << 3) + (lane & 7)) * (SSTR * 2)
                                           + ((lane >> 3) & 1) * 16);

    float4 xr[4];   // half-chunk staging: 32 rows x 64 fp32 = 512 float4

    auto load_xh = [&](int c, int h) {
        #pragma unroll
        for (int it = 0; it < 4; it++) {
            int slot = it * NTHREADS + tid;          // 0..511
            int r = h * 32 + (slot >> 4);            // 16 float4 per row
            int c4 = (slot & 15) * 4;
            xr[it] = *(const float4*)(xblk + (size_t)r * KDIM + c * BK + c4);
        }
    };
    auto sts_xh = [&](int c, int h) {
        uint32_t dA = sbase + (c & 1) * STAGE_BYTES;
        #pragma unroll
        for (int it = 0; it < 4; it++) {
            int slot = it * NTHREADS + tid;
            int r = h * 32 + (slot >> 4);
            int c4 = (slot & 15) * 4;
            uint32_t h01 = pack2h(xr[it].x, xr[it].y);
            uint32_t h23 = pack2h(xr[it].z, xr[it].w);
            uint32_t doff = (uint32_t)(r * (SSTR * 2) + c4 * 2);
            asm volatile("st.shared.v2.b32 [%0], {%1,%2};" :: "r"(dA + doff), "r"(h01), "r"(h23));
        }
    };
    auto cp_B = [&](int c) {
        uint32_t dB = sbase + (c & 1) * STAGE_BYTES + ATILE;
        #pragma unroll
        for (int it = 0; it < 8; it++) {
            int slot = it * NTHREADS + tid;          // 0..1023
            int r = slot >> 3, seg = slot & 7;       // 8 x 16B per row
            uint32_t doff = (uint32_t)(r * (SSTR * 2) + seg * 16);
            size_t goff = (size_t)r * KDIM + c * BK + seg * 8;
            cp_async16(dB + doff, gBh + goff);
        }
        CP_COMMIT();
    };

    auto mma_group = [&](int c, int k0, int k1) {
        const uint32_t Ah = sbase + (c & 1) * STAGE_BYTES;
        const uint32_t Bh = Ah + ATILE;
        #pragma unroll
        for (int ks = k0; ks < k1; ks++) {
            const uint32_t kso = ks * 32;
            uint32_t af[2][4], bh[4][4];
            #pragma unroll
            for (int mi = 0; mi < 2; mi++)
                ldsm_x4(af[mi][0], af[mi][1], af[mi][2], af[mi][3],
                        Ah + a_lane_off + mi * 16 * (SSTR * 2) + kso);
            #pragma unroll
            for (int pj = 0; pj < 4; pj++)
                ldsm_x4(bh[pj][0], bh[pj][1], bh[pj][2], bh[pj][3],
                        Bh + b_lane_off + pj * 16 * (SSTR * 2) + kso);
            #pragma unroll
            for (int mi = 0; mi < 2; mi++)
                #pragma unroll
                for (int ni = 0; ni < 8; ni++)
                    mma_f16(acc[mi][ni][0], acc[mi][ni][1], acc[mi][ni][2], acc[mi][ni][3],
                            af[mi][0], af[mi][1], af[mi][2], af[mi][3],
                            bh[ni >> 1][(ni & 1) * 2], bh[ni >> 1][(ni & 1) * 2 + 1]);
        }
    };

    // prologue: stage chunk 0
    cp_B(0);
    load_xh(0, 0); sts_xh(0, 0);
    load_xh(0, 1); sts_xh(0, 1);
    CP_WAIT0();
    __syncthreads();

    for (int c = 0; c < NCHUNK; c++) {
        if (c + 1 < NCHUNK) {
            cp_B(c + 1);
            load_xh(c + 1, 0);
            mma_group(c, 0, 2);
            sts_xh(c + 1, 0);
            load_xh(c + 1, 1);
            mma_group(c, 2, 4);
            sts_xh(c + 1, 1);
            CP_WAIT0();
        } else {
            mma_group(c, 0, 4);
        }
        __syncthreads();
    }

    // ---- epilogue: registers -> global (float2 stores) + bias ----
    float* oblk = out + (size_t)bm * BM * NDIM + bn * BN;
    const int r0 = wm * 32 + (lane >> 2);
    const int c0 = wn * 64 + (lane & 3) * 2;
    #pragma unroll
    for (int ni = 0; ni < 8; ni++) {
        const int col = c0 + ni * 8;
        const float b0 = bias[col & 31];
        const float b1 = bias[(col + 1) & 31];
        #pragma unroll
        for (int mi = 0; mi < 2; mi++) {
            const int row = r0 + mi * 16;
            float2 v0 = make_float2(acc[mi][ni][0] + b0, acc[mi][ni][1] + b1);
            float2 v1 = make_float2(acc[mi][ni][2] + b0, acc[mi][ni][3] + b1);
            *(float2*)(oblk + (size_t)row * NDIM + col) = v0;
            *(float2*)(oblk + (size_t)(row + 8) * NDIM + col) = v1;
        }
    }
}

// ---------------------------------------------------------------------------
extern "C" void kernel_launch(void* const* d_in, const int* in_sizes, int n_in,
                              void* d_out, int out_size) {
    const float* x    = (const float*)d_in[0];   // [400000, 384]
    const float* edge = (const float*)d_in[1];   // [12, 12, 3]
    const float* W    = (const float*)d_in[2];   // [1024, 3]
    const float* bias = (const float*)d_in[3];   // [32]
    float* out = (float*)d_out;                  // [400000, 384]

    cudaFuncSetAttribute(fiber_gemm_hmma,
                         cudaFuncAttributeMaxDynamicSharedMemorySize, SMEM_DYN);

    fiber_precompute<<<(NDIM * KDIM + 255) / 256, 256>>>(edge, W);

    dim3 grid(NDIM / BN, BATCH / BM);   // (3, 6250)
    fiber_gemm_hmma<<<grid, NTHREADS, SMEM_DYN>>>(x, bias, out);
}